// round 1
// baseline (speedup 1.0000x reference)
#include <cuda_runtime.h>

// Problem constants
#define BS   64
#define CIN  128
#define COUT 128
#define HH   56
#define WW   56
#define KEXP 8
#define PERB (COUT*CIN*9)      // 147456 weights per expert / per sample

// Scratch: mixed weights stored TRANSPOSED as [b][cin][3*3][cout] so the conv
// kernel's shared-memory weight loads are fully coalesced.
__device__ float g_wmix[(size_t)BS * CIN * 9 * COUT];   // 37.75 MB
__device__ float g_bmix[BS * COUT];

// ---------------------------------------------------------------------------
// Kernel 1: mix expert weights per sample.
//   reads weight in its native layout (coalesced), writes transposed layout.
// ---------------------------------------------------------------------------
__global__ __launch_bounds__(256)
void mix_kernel(const float* __restrict__ routing,   // [BS, KEXP]
                const float* __restrict__ weight)    // [KEXP, COUT, CIN, 3,3]
{
    int idx = blockIdx.x * 256 + threadIdx.x;        // over BS*PERB = 9437184
    if (idx >= BS * PERB) return;
    int b   = idx / PERB;
    int rem = idx - b * PERB;                        // = oc*CIN*9 + c*9 + f
    const float* rp = routing + b * KEXP;
    const float* wp = weight + rem;
    float s = 0.f;
#pragma unroll
    for (int k = 0; k < KEXP; k++)
        s += rp[k] * wp[(size_t)k * PERB];
    // decompose rem for the transposed write
    int oc = rem / (CIN * 9);
    int r2 = rem - oc * (CIN * 9);
    int c  = r2 / 9;
    int f  = r2 - c * 9;
    g_wmix[((size_t)(b * CIN + c) * 9 + f) * COUT + oc] = s;
}

// ---------------------------------------------------------------------------
// Kernel 2: mix bias per sample.
// ---------------------------------------------------------------------------
__global__ __launch_bounds__(256)
void bias_kernel(const float* __restrict__ routing,  // [BS, KEXP]
                 const float* __restrict__ bias)     // [KEXP, COUT]
{
    int idx = blockIdx.x * 256 + threadIdx.x;        // 8192
    if (idx >= BS * COUT) return;
    int b = idx / COUT, oc = idx - b * COUT;
    float s = 0.f;
#pragma unroll
    for (int k = 0; k < KEXP; k++)
        s += routing[b * KEXP + k] * bias[k * COUT + oc];
    g_bmix[idx] = s;
}

// ---------------------------------------------------------------------------
// Kernel 3: per-sample 3x3 conv, smem-staged direct conv.
// Block: (row_tile[14], oc_tile[4], b[64]); 256 threads.
// Block computes 32 oc x 4 rows x 56 cols. Thread: 4 oc x 7 cols (28 acc).
// ---------------------------------------------------------------------------
#define OCT  32     // oc per block
#define CCH  8      // cin per chunk
#define RT   4      // output rows per block
#define XH   6      // halo rows in smem (RT+2)
#define XW   58     // halo cols in smem (WW+2)

__global__ __launch_bounds__(256)
void conv_kernel(const float* __restrict__ x,        // [BS, CIN, H, W]
                 float* __restrict__ out)            // [BS, COUT, H, W]
{
    __shared__ float sX[CCH][XH][XW];                // 11136 B
    __shared__ float sW[CCH][9][OCT];                // 9216 B

    const int b     = blockIdx.z;
    const int oc_t  = blockIdx.y;
    const int row_t = blockIdx.x;
    const int tid   = threadIdx.x;

    const int oc_idx = tid & 7;          // 0..7  -> oc group of 4
    const int sp     = tid >> 3;         // 0..31 -> spatial group
    const int row    = sp >> 3;          // 0..3
    const int col0   = (sp & 7) * 7;     // 0,7,...,49

    float acc[4][7];
#pragma unroll
    for (int u = 0; u < 4; u++)
#pragma unroll
        for (int j = 0; j < 7; j++) acc[u][j] = 0.f;

    const float* xb = x + (size_t)b * CIN * HH * WW;
    const float* wb = g_wmix + (size_t)b * CIN * 9 * COUT + oc_t * OCT;

    const int oh = row_t * RT + row;

    for (int cc = 0; cc < CIN; cc += CCH) {
        // ---- load x halo tile: CCH x XH x XW = 2784 elems ----
        for (int i = tid; i < CCH * XH * XW; i += 256) {
            int c  = i / (XH * XW);
            int r2 = i - c * (XH * XW);
            int r  = r2 / XW;
            int cl = r2 - r * XW;
            int gh = row_t * RT + r - 1;
            int gw = cl - 1;
            float v = 0.f;
            if ((unsigned)gh < HH && (unsigned)gw < WW)
                v = xb[(size_t)(cc + c) * HH * WW + gh * WW + gw];
            sX[c][r][cl] = v;
        }
        // ---- load weight chunk: CCH x 9 x OCT = 2304 elems (coalesced) ----
        for (int i = tid; i < CCH * 9 * OCT; i += 256) {
            int c  = i / (9 * OCT);
            int r2 = i - c * (9 * OCT);
            int f  = r2 / OCT;
            int oc = r2 - f * OCT;
            sW[c][f][oc] = wb[((size_t)(cc + c) * 9 + f) * COUT + oc];
        }
        __syncthreads();

        // ---- compute ----
#pragma unroll
        for (int c = 0; c < CCH; c++) {
#pragma unroll
            for (int fh = 0; fh < 3; fh++) {
                float xr[9];
#pragma unroll
                for (int j = 0; j < 9; j++)
                    xr[j] = sX[c][row + fh][col0 + j];
#pragma unroll
                for (int fw = 0; fw < 3; fw++) {
                    const float4 wv =
                        *(const float4*)&sW[c][fh * 3 + fw][oc_idx * 4];
#pragma unroll
                    for (int j = 0; j < 7; j++) {
                        const float xv = xr[j + fw];
                        acc[0][j] += wv.x * xv;
                        acc[1][j] += wv.y * xv;
                        acc[2][j] += wv.z * xv;
                        acc[3][j] += wv.w * xv;
                    }
                }
            }
        }
        __syncthreads();
    }

    // ---- epilogue: add mixed bias, store ----
    const int ocg = oc_t * OCT + oc_idx * 4;
#pragma unroll
    for (int u = 0; u < 4; u++) {
        const float bm = g_bmix[b * COUT + ocg + u];
        float* op = out + (((size_t)b * COUT + ocg + u) * HH + oh) * WW + col0;
#pragma unroll
        for (int j = 0; j < 7; j++)
            op[j] = acc[u][j] + bm;
    }
}

// ---------------------------------------------------------------------------
extern "C" void kernel_launch(void* const* d_in, const int* in_sizes, int n_in,
                              void* d_out, int out_size)
{
    const float* x       = (const float*)d_in[0];   // [64,128,56,56]
    const float* routing = (const float*)d_in[1];   // [64,8]
    const float* weight  = (const float*)d_in[2];   // [8,128,128,3,3]
    const float* bias    = (const float*)d_in[3];   // [8,128]
    float* out           = (float*)d_out;           // [64,128,56,56]

    mix_kernel<<<(BS * PERB + 255) / 256, 256>>>(routing, weight);
    bias_kernel<<<(BS * COUT + 255) / 256, 256>>>(routing, bias);

    dim3 grid(HH / RT, COUT / OCT, BS);             // (14, 4, 64)
    conv_kernel<<<grid, 256>>>(x, out);
}

// round 3
// speedup vs baseline: 5.8420x; 5.8420x over previous
#include <cuda_runtime.h>
#include <cuda_fp16.h>
#include <cstdint>

// ---------------------------------------------------------------------------
// Problem constants
// ---------------------------------------------------------------------------
#define BS    64
#define CIN   128
#define COUT  128
#define HH    56
#define WW    56
#define PADW  58
#define VROWS (PADW*PADW)   // 3364 meaningful padded-raster rows
#define NR2   3584          // allocated rows per sample (covers 27*128+59, zero tail)
#define MT    27            // m-tiles of 128
#define KCH   18            // 9 taps x 2 cin-chunks of 64
#define STAGE_BYTES 32768   // A tile 16KB + B tile 16KB
#define SMEM_TOTAL  (3*STAGE_BYTES)

// ---------------------------------------------------------------------------
// Scratch (device globals; no runtime allocation)
// ---------------------------------------------------------------------------
__device__ __half g_xt[(size_t)BS * NR2 * CIN];          // 58.7 MB
__device__ __half g_wt[(size_t)BS * 9 * COUT * CIN];     // 18.9 MB
__device__ float  g_bmix[BS * COUT];

// ---------------------------------------------------------------------------
// PTX helpers
// ---------------------------------------------------------------------------
__device__ __forceinline__ uint32_t smem_u32(const void* p) {
    uint32_t a;
    asm("{ .reg .u64 t; cvta.to.shared.u64 t, %1; cvt.u32.u64 %0, t; }"
        : "=r"(a) : "l"(p));
    return a;
}
__device__ __forceinline__ void cp16(uint32_t dst, const void* src) {
    asm volatile("cp.async.cg.shared.global [%0], [%1], 16;"
                 :: "r"(dst), "l"(__cvta_generic_to_global(src)) : "memory");
}
__device__ __forceinline__ void cp_commit() {
    asm volatile("cp.async.commit_group;" ::: "memory");
}
template <int N>
__device__ __forceinline__ void cp_wait() {
    asm volatile("cp.async.wait_group %0;" :: "n"(N) : "memory");
}
__device__ __forceinline__ void ldsm4(uint32_t* r, uint32_t addr) {
    asm volatile("ldmatrix.sync.aligned.m8n8.x4.shared.b16 {%0,%1,%2,%3}, [%4];"
                 : "=r"(r[0]), "=r"(r[1]), "=r"(r[2]), "=r"(r[3]) : "r"(addr));
}
__device__ __forceinline__ void mma16816(float* c, const uint32_t* a, const uint32_t* b) {
    asm volatile(
        "mma.sync.aligned.m16n8k16.row.col.f32.f16.f16.f32 "
        "{%0,%1,%2,%3}, {%4,%5,%6,%7}, {%8,%9}, {%0,%1,%2,%3};"
        : "+f"(c[0]), "+f"(c[1]), "+f"(c[2]), "+f"(c[3])
        : "r"(a[0]), "r"(a[1]), "r"(a[2]), "r"(a[3]), "r"(b[0]), "r"(b[1]));
}

// ---------------------------------------------------------------------------
// Kernel 1: x -> padded raster fp16  xt[b][r=h'*58+w'][c], zero borders/tail.
// ---------------------------------------------------------------------------
__global__ __launch_bounds__(256)
void transform_kernel(const float* __restrict__ x)
{
    __shared__ float s[128][33];
    const int b = blockIdx.y;
    const int r0 = blockIdx.x * 32;
    const int warp = threadIdx.x >> 5, lane = threadIdx.x & 31;

    for (int c = warp; c < 128; c += 8) {
        int r = r0 + lane;
        int hp = r / PADW, wp = r - hp * PADW;
        float v = 0.f;
        if (r < VROWS && hp >= 1 && hp < 57 && wp >= 1 && wp < 57)
            v = x[((size_t)b * CIN + c) * (HH * WW) + (hp - 1) * WW + (wp - 1)];
        s[c][lane] = v;
    }
    __syncthreads();
    for (int i = threadIdx.x; i < 128 * 32; i += 256) {
        int rr = i >> 7, c = i & 127;
        g_xt[((size_t)b * NR2 + r0 + rr) * CIN + c] = __float2half(s[c][rr]);
    }
}

// ---------------------------------------------------------------------------
// Kernel 2: expert-mix weights -> fp16, layout [b][f][oc][c].
// ---------------------------------------------------------------------------
__global__ __launch_bounds__(128)
void mix_kernel(const float* __restrict__ routing,   // [BS, 8]
                const float* __restrict__ weight)    // [8, COUT, CIN, 3,3]
{
    __shared__ float sr[BS * 8];
    for (int i = threadIdx.x; i < BS * 8; i += 128) sr[i] = routing[i];
    __syncthreads();

    int idx = blockIdx.x * 128 + threadIdx.x;        // (f*128+oc)*128 + c
    int c  = idx & 127;
    int t  = idx >> 7;
    int oc = t & 127;
    int f  = t >> 7;                                 // 0..8

    float w[8];
#pragma unroll
    for (int k = 0; k < 8; k++)
        w[k] = weight[(((size_t)k * COUT + oc) * CIN + c) * 9 + f];

    for (int b = 0; b < BS; b++) {
        float s = 0.f;
#pragma unroll
        for (int k = 0; k < 8; k++) s += sr[b * 8 + k] * w[k];
        g_wt[(((size_t)b * 9 + f) * COUT + oc) * CIN + c] = __float2half(s);
    }
}

// ---------------------------------------------------------------------------
// Kernel 3: bias mix.
// ---------------------------------------------------------------------------
__global__ __launch_bounds__(256)
void bias_kernel(const float* __restrict__ routing, const float* __restrict__ bias)
{
    int idx = blockIdx.x * 256 + threadIdx.x;
    if (idx >= BS * COUT) return;
    int b = idx / COUT, oc = idx - b * COUT;
    float s = 0.f;
#pragma unroll
    for (int k = 0; k < 8; k++)
        s += routing[b * 8 + k] * bias[k * COUT + oc];
    g_bmix[idx] = s;
}

// ---------------------------------------------------------------------------
// Kernel 4: implicit-GEMM conv via mma.sync (HMMA).
//   CTA: sample b x m-tile (128 rows x 128 oc). 8 warps = 2(m) x 4(n),
//   warp tile 64x32, 3-stage cp.async pipeline, k-chunk 64.
// ---------------------------------------------------------------------------
__global__ __launch_bounds__(256, 2)
void conv_kernel(float* __restrict__ out)
{
    extern __shared__ char smem[];
    const uint32_t sbase = smem_u32(smem);
    const int tid  = threadIdx.x;
    const int wid  = tid >> 5;
    const int lane = tid & 31;
    const int b  = blockIdx.y;
    const int m_base = blockIdx.x * 128;

    const int wm = (wid >> 2) * 64;          // warp m offset
    const int wn = (wid & 3) * 32;           // warp n offset
    const int gid = lane >> 2, tig = lane & 3;

    const __half* xt = g_xt + (size_t)b * NR2 * CIN;
    const __half* wt = g_wt + (size_t)b * 9 * COUT * CIN;

    float c[4][4][4];
#pragma unroll
    for (int mi = 0; mi < 4; mi++)
#pragma unroll
        for (int ni = 0; ni < 4; ni++)
#pragma unroll
            for (int k = 0; k < 4; k++) c[mi][ni][k] = 0.f;

    // cp.async loader: thread -> (row = tid>>3 + 32*it, 16B piece j = tid&7)
    const int lr = tid >> 3, lj = tid & 7;

    auto load_stage = [&](int g, int s) {
        int f = g >> 1, cc = (g & 1) * 64;
        int shift = (f / 3) * PADW + (f % 3);
        const __half* gA = xt + ((size_t)(m_base + shift)) * CIN + cc;
        const __half* gB = wt + ((size_t)f * COUT) * CIN + cc;
        uint32_t sA = sbase + s * STAGE_BYTES;
        uint32_t sB = sA + 16384;
#pragma unroll
        for (int it = 0; it < 4; it++) {
            int row = lr + it * 32;
            uint32_t dchunk = (uint32_t)(lj ^ (row & 7));
            cp16(sA + row * 128 + dchunk * 16, gA + (size_t)row * CIN + lj * 8);
            cp16(sB + row * 128 + dchunk * 16, gB + (size_t)row * CIN + lj * 8);
        }
        cp_commit();
    };

    // prologue
    load_stage(0, 0);
    load_stage(1, 1);

    const int x7 = lane & 7;
    // A frag addressing: row = wm + mi*16 + (lane&15), chunk = ks*2 + (lane>>4)
    const int a_row = wm + (lane & 15);
    const int a_cbase = lane >> 4;
    // B frag addressing: row = wn + nj*16 + ((lane>>4)<<3) + (lane&7), chunk = ks*2 + ((lane>>3)&1)
    const int b_row = wn + ((lane >> 4) << 3) + (lane & 7);
    const int b_cbase = (lane >> 3) & 1;

    for (int g = 0; g < KCH; g++) {
        if (g < KCH - 1) cp_wait<1>(); else cp_wait<0>();
        __syncthreads();
        if (g + 2 < KCH) load_stage(g + 2, (g + 2) % 3);

        const int s = g % 3;
        const uint32_t sA = sbase + s * STAGE_BYTES;
        const uint32_t sB = sA + 16384;
        const uint32_t baseA = sA + (uint32_t)a_row * 128;
        const uint32_t baseB = sB + (uint32_t)b_row * 128;

#pragma unroll
        for (int ks = 0; ks < 4; ks++) {
            uint32_t a[4][4], bb[2][4];
#pragma unroll
            for (int mi = 0; mi < 4; mi++) {
                uint32_t ch = (uint32_t)((ks * 2 + a_cbase) ^ x7);
                ldsm4(a[mi], baseA + mi * 16 * 128 + ch * 16);
            }
#pragma unroll
            for (int nj = 0; nj < 2; nj++) {
                uint32_t ch = (uint32_t)((ks * 2 + b_cbase) ^ x7);
                ldsm4(bb[nj], baseB + nj * 16 * 128 + ch * 16);
            }
#pragma unroll
            for (int mi = 0; mi < 4; mi++)
#pragma unroll
                for (int ni = 0; ni < 4; ni++)
                    mma16816(c[mi][ni], a[mi], &bb[ni >> 1][(ni & 1) * 2]);
        }
        __syncthreads();   // stage consumed; safe for reuse by load in next iters
    }

    // ---------------- epilogue: transpose through smem, coalesced stores ----
    float* sC = (float*)smem;                 // [oc][m], stride 129 (66048 B)
#pragma unroll
    for (int mi = 0; mi < 4; mi++) {
#pragma unroll
        for (int ni = 0; ni < 4; ni++) {
            int m  = wm + mi * 16 + gid;
            int oc = wn + ni * 8 + 2 * tig;
            sC[oc * 129 + m]             = c[mi][ni][0];
            sC[(oc + 1) * 129 + m]       = c[mi][ni][1];
            sC[oc * 129 + m + 8]         = c[mi][ni][2];
            sC[(oc + 1) * 129 + m + 8]   = c[mi][ni][3];
        }
    }
    __syncthreads();

    const float* bm = g_bmix + b * COUT;
    float* ob = out + (size_t)b * COUT * (HH * WW);
    for (int idx = tid; idx < 128 * 128; idx += 256) {
        int oc = idx >> 7, m = idx & 127;
        int p = m_base + m;
        int h = p / PADW;
        int w = p - h * PADW;
        if (h < HH && w < WW)
            ob[(size_t)oc * (HH * WW) + h * WW + w] = sC[oc * 129 + m] + __ldg(&bm[oc]);
    }
}

// ---------------------------------------------------------------------------
extern "C" void kernel_launch(void* const* d_in, const int* in_sizes, int n_in,
                              void* d_out, int out_size)
{
    const float* x       = (const float*)d_in[0];   // [64,128,56,56]
    const float* routing = (const float*)d_in[1];   // [64,8]
    const float* weight  = (const float*)d_in[2];   // [8,128,128,3,3]
    const float* bias    = (const float*)d_in[3];   // [8,128]
    float* out           = (float*)d_out;           // [64,128,56,56]

    transform_kernel<<<dim3(NR2 / 32, BS), 256>>>(x);
    mix_kernel<<<(9 * COUT * CIN) / 128, 128>>>(routing, weight);
    bias_kernel<<<(BS * COUT + 255) / 256, 256>>>(routing, bias);

    static int attr_set = 0;
    if (!attr_set) {
        cudaFuncSetAttribute(conv_kernel,
                             cudaFuncAttributeMaxDynamicSharedMemorySize, SMEM_TOTAL);
        attr_set = 1;
    }
    conv_kernel<<<dim3(MT, BS), 256, SMEM_TOTAL>>>(out);
}

// round 5
// speedup vs baseline: 6.6682x; 1.1414x over previous
#include <cuda_runtime.h>
#include <cuda_fp16.h>
#include <cstdint>

// ---------------------------------------------------------------------------
// Problem constants
// ---------------------------------------------------------------------------
#define BS    64
#define CIN   128
#define COUT  128
#define HH    56
#define WW    56
#define PADW  58
#define VROWS (PADW*PADW)   // 3364 meaningful padded-raster rows
#define NR2   3584          // allocated rows per sample (covers 26*128+127+59, zero tail)
#define MT    27            // m-tiles of 128
#define KCH   18            // 9 taps x 2 cin-chunks of 64
#define STAGE_BYTES 32768   // A tile 16KB + B tile 16KB
#define SMEM_TOTAL  (3*STAGE_BYTES)

// ---------------------------------------------------------------------------
// Scratch (device globals; no runtime allocation)
// ---------------------------------------------------------------------------
__device__ __half g_xt[(size_t)BS * NR2 * CIN];          // 58.7 MB
__device__ __half g_wt[(size_t)BS * 9 * COUT * CIN];     // 18.9 MB
__device__ float  g_bmix[BS * COUT];

// ---------------------------------------------------------------------------
// PTX helpers
// ---------------------------------------------------------------------------
__device__ __forceinline__ uint32_t smem_u32(const void* p) {
    uint32_t a;
    asm("{ .reg .u64 t; cvta.to.shared.u64 t, %1; cvt.u32.u64 %0, t; }"
        : "=r"(a) : "l"(p));
    return a;
}
__device__ __forceinline__ void cp16(uint32_t dst, const void* src) {
    asm volatile("cp.async.cg.shared.global [%0], [%1], 16;"
                 :: "r"(dst), "l"(__cvta_generic_to_global(src)) : "memory");
}
__device__ __forceinline__ void cp_commit() {
    asm volatile("cp.async.commit_group;" ::: "memory");
}
template <int N>
__device__ __forceinline__ void cp_wait() {
    asm volatile("cp.async.wait_group %0;" :: "n"(N) : "memory");
}
__device__ __forceinline__ void ldsm4(uint32_t* r, uint32_t addr) {
    asm volatile("ldmatrix.sync.aligned.m8n8.x4.shared.b16 {%0,%1,%2,%3}, [%4];"
                 : "=r"(r[0]), "=r"(r[1]), "=r"(r[2]), "=r"(r[3]) : "r"(addr));
}
__device__ __forceinline__ void mma16816(float* c, const uint32_t* a, const uint32_t* b) {
    asm volatile(
        "mma.sync.aligned.m16n8k16.row.col.f32.f16.f16.f32 "
        "{%0,%1,%2,%3}, {%4,%5,%6,%7}, {%8,%9}, {%0,%1,%2,%3};"
        : "+f"(c[0]), "+f"(c[1]), "+f"(c[2]), "+f"(c[3])
        : "r"(a[0]), "r"(a[1]), "r"(a[2]), "r"(a[3]), "r"(b[0]), "r"(b[1]));
}

// ---------------------------------------------------------------------------
// Kernel 1: x -> padded raster fp16  xt[b][r=h'*58+w'][c], zero borders/tail.
//   s[channel][row] layout: phase-1 writes conflict-free; phase-2 gathers 8
//   scalar floats (stride 33 = bank-stride 1, conflict-free) -> one 16B store.
// ---------------------------------------------------------------------------
__global__ __launch_bounds__(256)
void transform_kernel(const float* __restrict__ x)
{
    __shared__ float s[128][33];
    const int b = blockIdx.y;
    const int r0 = blockIdx.x * 32;
    const int warp = threadIdx.x >> 5, lane = threadIdx.x & 31;

    {
        const int r = r0 + lane;
        const int hp = r / PADW, wp = r - hp * PADW;
        const bool ok = (r < VROWS) && (hp >= 1) && (hp < 57) && (wp >= 1) && (wp < 57);
        const float* xr = x + (size_t)b * CIN * (HH * WW) + (hp - 1) * WW + (wp - 1);
#pragma unroll
        for (int k = 0; k < 16; k++) {
            const int c = warp + k * 8;
            s[c][lane] = ok ? xr[(size_t)c * (HH * WW)] : 0.f;
        }
    }
    __syncthreads();
#pragma unroll
    for (int i = threadIdx.x; i < 32 * 16; i += 256) {
        const int rr = i >> 4;
        const int c0 = (i & 15) * 8;
        __half h[8];
#pragma unroll
        for (int j = 0; j < 8; j++)
            h[j] = __float2half(s[c0 + j][rr]);
        *(uint4*)&g_xt[((size_t)b * NR2 + r0 + rr) * CIN + c0] = *(const uint4*)h;
    }
}

// ---------------------------------------------------------------------------
// Kernel 2: expert-mix weights -> fp16, layout [b][f][oc][c]; bias fused.
//   Grid (COUT, 9): block = (oc, f). All 64 samples in parallel.
// ---------------------------------------------------------------------------
__global__ __launch_bounds__(256)
void mix_kernel(const float* __restrict__ routing,   // [BS, 8]
                const float* __restrict__ weight,    // [8, COUT, CIN, 3,3]
                const float* __restrict__ bias)      // [8, COUT]
{
    __shared__ float r_s[64][8];      // 2 KB
    __shared__ float w_s[8][128];     // 4 KB
    const int oc = blockIdx.x;
    const int f  = blockIdx.y;
    const int tid = threadIdx.x;

    for (int i = tid; i < 64 * 8; i += 256)
        ((float*)r_s)[i] = routing[i];
    for (int i = tid; i < 8 * 128; i += 256) {
        const int k = i >> 7, c = i & 127;
        w_s[k][c] = weight[(((size_t)k * COUT + oc) * CIN + c) * 9 + f];
    }
    __syncthreads();

    const int warp = tid >> 5, lane = tid & 31;
    const int c0 = lane * 4;
#pragma unroll
    for (int bi = 0; bi < 8; bi++) {
        const int b = warp + bi * 8;
        const float* rb = r_s[b];
        float s0 = 0.f, s1 = 0.f, s2 = 0.f, s3 = 0.f;
#pragma unroll
        for (int k = 0; k < 8; k++) {
            const float r = rb[k];
            s0 += r * w_s[k][c0];
            s1 += r * w_s[k][c0 + 1];
            s2 += r * w_s[k][c0 + 2];
            s3 += r * w_s[k][c0 + 3];
        }
        __half h[4];
        h[0] = __float2half(s0); h[1] = __float2half(s1);
        h[2] = __float2half(s2); h[3] = __float2half(s3);
        *(uint2*)&g_wt[(((size_t)b * 9 + f) * COUT + oc) * CIN + c0] = *(const uint2*)h;
    }

    // fused bias mix (one block column does it)
    if (f == 0 && tid < 64) {
        float s = 0.f;
#pragma unroll
        for (int k = 0; k < 8; k++)
            s += r_s[tid][k] * bias[k * COUT + oc];
        g_bmix[tid * COUT + oc] = s;
    }
}

// ---------------------------------------------------------------------------
// Kernel 3: implicit-GEMM conv via mma.sync (HMMA).
//   CTA: sample b x m-tile (128 rows x 128 oc). 8 warps = 2(m) x 4(n),
//   warp tile 64x32, 3-stage cp.async pipeline, k-chunk 64, ONE sync/iter.
// ---------------------------------------------------------------------------
__global__ __launch_bounds__(256, 2)
void conv_kernel(float* __restrict__ out)
{
    extern __shared__ char smem[];
    const uint32_t sbase = smem_u32(smem);
    const int tid  = threadIdx.x;
    const int wid  = tid >> 5;
    const int lane = tid & 31;
    const int b  = blockIdx.y;
    const int m_base = blockIdx.x * 128;

    const int wm = (wid >> 2) * 64;          // warp m offset
    const int wn = (wid & 3) * 32;           // warp n offset
    const int gid = lane >> 2, tig = lane & 3;

    const __half* xt = g_xt + (size_t)b * NR2 * CIN;
    const __half* wt = g_wt + (size_t)b * 9 * COUT * CIN;

    float c[4][4][4];
#pragma unroll
    for (int mi = 0; mi < 4; mi++)
#pragma unroll
        for (int ni = 0; ni < 4; ni++)
#pragma unroll
            for (int k = 0; k < 4; k++) c[mi][ni][k] = 0.f;

    // cp.async loader: thread -> (row = tid>>3 + 32*it, 16B piece j = tid&7)
    const int lr = tid >> 3, lj = tid & 7;

    auto load_stage = [&](int g, int s) {
        int f = g >> 1, cc = (g & 1) * 64;
        int shift = (f / 3) * PADW + (f % 3);
        const __half* gA = xt + ((size_t)(m_base + shift)) * CIN + cc;
        const __half* gB = wt + ((size_t)f * COUT) * CIN + cc;
        uint32_t sA = sbase + s * STAGE_BYTES;
        uint32_t sB = sA + 16384;
#pragma unroll
        for (int it = 0; it < 4; it++) {
            int row = lr + it * 32;
            uint32_t dchunk = (uint32_t)(lj ^ (row & 7));
            cp16(sA + row * 128 + dchunk * 16, gA + (size_t)row * CIN + lj * 8);
            cp16(sB + row * 128 + dchunk * 16, gB + (size_t)row * CIN + lj * 8);
        }
        cp_commit();
    };

    // prologue
    load_stage(0, 0);
    load_stage(1, 1);

    const int x7 = lane & 7;
    const int a_row = wm + (lane & 15);
    const int a_cbase = lane >> 4;
    const int b_row = wn + ((lane >> 4) << 3) + (lane & 7);
    const int b_cbase = (lane >> 3) & 1;

    for (int g = 0; g < KCH; g++) {
        if (g < KCH - 1) cp_wait<1>(); else cp_wait<0>();
        __syncthreads();   // stage g visible to all; also fences prior-iter reads
        if (g + 2 < KCH) load_stage(g + 2, (g + 2) % 3);

        const int s = g % 3;
        const uint32_t sA = sbase + s * STAGE_BYTES;
        const uint32_t sB = sA + 16384;
        const uint32_t baseA = sA + (uint32_t)a_row * 128;
        const uint32_t baseB = sB + (uint32_t)b_row * 128;

#pragma unroll
        for (int ks = 0; ks < 4; ks++) {
            uint32_t a[4][4], bb[2][4];
#pragma unroll
            for (int mi = 0; mi < 4; mi++) {
                uint32_t ch = (uint32_t)((ks * 2 + a_cbase) ^ x7);
                ldsm4(a[mi], baseA + mi * 16 * 128 + ch * 16);
            }
#pragma unroll
            for (int nj = 0; nj < 2; nj++) {
                uint32_t ch = (uint32_t)((ks * 2 + b_cbase) ^ x7);
                ldsm4(bb[nj], baseB + nj * 16 * 128 + ch * 16);
            }
#pragma unroll
            for (int mi = 0; mi < 4; mi++)
#pragma unroll
                for (int ni = 0; ni < 4; ni++)
                    mma16816(c[mi][ni], a[mi], &bb[ni >> 1][(ni & 1) * 2]);
        }
        // no trailing sync: next iter's top sync orders reuse of this stage
    }
    __syncthreads();   // all ldsm done before smem reuse as sC

    // ---------------- epilogue: transpose through smem, coalesced stores ----
    float* sC = (float*)smem;                 // [oc][m], stride 129 (66048 B)
#pragma unroll
    for (int mi = 0; mi < 4; mi++) {
#pragma unroll
        for (int ni = 0; ni < 4; ni++) {
            int m  = wm + mi * 16 + gid;
            int oc = wn + ni * 8 + 2 * tig;
            sC[oc * 129 + m]             = c[mi][ni][0];
            sC[(oc + 1) * 129 + m]       = c[mi][ni][1];
            sC[oc * 129 + m + 8]         = c[mi][ni][2];
            sC[(oc + 1) * 129 + m + 8]   = c[mi][ni][3];
        }
    }
    __syncthreads();

    const float* bm = g_bmix + b * COUT;
    float* ob = out + (size_t)b * COUT * (HH * WW);
    for (int idx = tid; idx < 128 * 128; idx += 256) {
        int oc = idx >> 7, m = idx & 127;
        int p = m_base + m;
        int h = p / PADW;
        int w = p - h * PADW;
        if (h < HH && w < WW)
            ob[(size_t)oc * (HH * WW) + h * WW + w] = sC[oc * 129 + m] + __ldg(&bm[oc]);
    }
}

// ---------------------------------------------------------------------------
extern "C" void kernel_launch(void* const* d_in, const int* in_sizes, int n_in,
                              void* d_out, int out_size)
{
    const float* x       = (const float*)d_in[0];   // [64,128,56,56]
    const float* routing = (const float*)d_in[1];   // [64,8]
    const float* weight  = (const float*)d_in[2];   // [8,128,128,3,3]
    const float* bias    = (const float*)d_in[3];   // [8,128]
    float* out           = (float*)d_out;           // [64,128,56,56]

    transform_kernel<<<dim3(NR2 / 32, BS), 256>>>(x);
    mix_kernel<<<dim3(COUT, 9), 256>>>(routing, weight, bias);

    static int attr_set = 0;
    if (!attr_set) {
        cudaFuncSetAttribute(conv_kernel,
                             cudaFuncAttributeMaxDynamicSharedMemorySize, SMEM_TOTAL);
        attr_set = 1;
    }
    conv_kernel<<<dim3(MT, BS), 256, SMEM_TOTAL>>>(out);
}